// round 16
// baseline (speedup 1.0000x reference)
#include <cuda_runtime.h>
#include <cuda_bf16.h>
#include <math.h>
#include <stdint.h>

// ---------------- problem constants ----------------
#define BATCH 2
#define QN    16384
#define CDIM  256
#define NHEAD 8
#define HDIM  32
#define NLVL  3
#define NPT   4
#define NV    13125
#define FDIM  1024
#define BQ    (BATCH*QN)       // 32768
#define BNV   (BATCH*NV)       // 26250

// ---------------- fp32 scratch ----------------
__device__ float g_oa  [BQ * 288];      // 1: fused offset(192)+attn(96) logits
__device__ float g_x   [BQ * CDIM];     // 2: post-attn residual
__device__ float g_bias_oa[288];        // concat bias for fused GEMM

// ---------------- bf16 activation scratch ----------------
__device__ __nv_bfloat16 b_q   [BQ * CDIM];    // 1: LN1+pos
__device__ __nv_bfloat16 b_vin [BNV * CDIM];   // 2: value (pre-rounded)
__device__ __nv_bfloat16 b_samp[BQ * CDIM];    // 3: deform out
__device__ __nv_bfloat16 b_h   [BQ * CDIM];    // 4: LN2 out
__device__ __nv_bfloat16 b_ffn [BQ * FDIM];    // 5: FFN hidden
__device__ __nv_bfloat16 b_vout[BNV * CDIM];   // 6: value projection (deform reads)

// ---------------- bf16 transposed weights [n][k] ----------------
__device__ __nv_bfloat16 w_v   [CDIM * CDIM];  // 1
__device__ __nv_bfloat16 w_oa  [288  * CDIM];  // 2 (rows 0..191 off, 192..287 attn)
__device__ __nv_bfloat16 w_outm[CDIM * CDIM];  // 3
__device__ __nv_bfloat16 w_f1  [FDIM * CDIM];  // 4
__device__ __nv_bfloat16 w_f2  [CDIM * FDIM];  // 5

template<int ID> __device__ __forceinline__ float* gbuf() {
    if constexpr (ID == 1) return g_oa;
    else if constexpr (ID == 2) return g_x;
    else return nullptr;
}
template<int ID> __device__ __forceinline__ __nv_bfloat16* gb16() {
    if constexpr (ID == 1) return b_q;
    else if constexpr (ID == 2) return b_vin;
    else if constexpr (ID == 3) return b_samp;
    else if constexpr (ID == 4) return b_h;
    else if constexpr (ID == 5) return b_ffn;
    else if constexpr (ID == 6) return b_vout;
    else return nullptr;
}
template<int ID> __device__ __forceinline__ __nv_bfloat16* gw16() {
    if constexpr (ID == 1) return w_v;
    else if constexpr (ID == 2) return w_oa;
    else if constexpr (ID == 3) return w_outm;
    else if constexpr (ID == 4) return w_f1;
    else if constexpr (ID == 5) return w_f2;
    else return nullptr;
}

// ---------------- shared LayerNorm row routine (256 threads per row) ------------
__device__ __forceinline__ void ln_row(const float* __restrict__ in,
                                       const float* __restrict__ gam,
                                       const float* __restrict__ bet,
                                       const float* __restrict__ add,
                                       __nv_bfloat16* __restrict__ out,
                                       float* red, float* s_mean, float* s_var,
                                       int row, int t)
{
    const size_t base = (size_t)row * CDIM;
    float x = in[base + t];

    float s = x;
    #pragma unroll
    for (int o = 16; o > 0; o >>= 1) s += __shfl_xor_sync(0xffffffffu, s, o);
    if ((t & 31) == 0) red[t >> 5] = s;
    __syncthreads();
    if (t < 32) {
        float v = (t < 8) ? red[t] : 0.f;
        #pragma unroll
        for (int o = 4; o > 0; o >>= 1) v += __shfl_xor_sync(0xffffffffu, v, o);
        if (t == 0) *s_mean = v * (1.0f / CDIM);
    }
    __syncthreads();
    const float mean = *s_mean;
    float dx = x - mean;

    float s2 = dx * dx;
    #pragma unroll
    for (int o = 16; o > 0; o >>= 1) s2 += __shfl_xor_sync(0xffffffffu, s2, o);
    __syncthreads();
    if ((t & 31) == 0) red[t >> 5] = s2;
    __syncthreads();
    if (t < 32) {
        float v = (t < 8) ? red[t] : 0.f;
        #pragma unroll
        for (int o = 4; o > 0; o >>= 1) v += __shfl_xor_sync(0xffffffffu, v, o);
        if (t == 0) *s_var = v * (1.0f / CDIM);
    }
    __syncthreads();
    float y = dx * rsqrtf(*s_var + 1e-5f) * gam[t] + bet[t];
    if (add) y += add[base + t];
    out[base + t] = __float2bfloat16_rn(y);
}

// ---------------- mega pre-pass: transposes + bias concat + value cvt + LN1 -----
// blocks [0,712): weight transpose tiles. block 712: bias concat.
// blocks [713, 713+6563): value fp32->bf16. blocks [7276, 7276+BQ): LN1 rows.
#define CVT_BLKS 6563
#define LN1_BASE (713 + CVT_BLKS)
__global__ void __launch_bounds__(256) prepass_all(
    const float* __restrict__ Wv,  const float* __restrict__ Woff,
    const float* __restrict__ Wat, const float* __restrict__ Wout,
    const float* __restrict__ Wf1, const float* __restrict__ Wf2,
    const float* __restrict__ boff, const float* __restrict__ batt,
    const float* __restrict__ value,
    const float* __restrict__ query, const float* __restrict__ qpos,
    const float* __restrict__ ln1g, const float* __restrict__ ln1b)
{
    __shared__ float t[32][33];
    const int b = blockIdx.x;
    const int tid = threadIdx.y * 32 + threadIdx.x;

    if (b >= LN1_BASE) {                  // LN1 rows
        __shared__ float red[8];
        __shared__ float s_mean, s_var;
        ln_row(query, ln1g, ln1b, qpos, b_q, red, &s_mean, &s_var,
               b - LN1_BASE, tid);
        return;
    }
    if (b >= 713) {                       // value fp32 -> bf16
        const size_t i = ((size_t)(b - 713) * 256 + tid) * 4;
        if (i + 3 < (size_t)BNV * CDIM) {
            float4 v = *(const float4*)(value + i);
            b_vin[i + 0] = __float2bfloat16_rn(v.x);
            b_vin[i + 1] = __float2bfloat16_rn(v.y);
            b_vin[i + 2] = __float2bfloat16_rn(v.z);
            b_vin[i + 3] = __float2bfloat16_rn(v.w);
        }
        return;
    }
    if (b == 712) {                       // bias concat
        if (tid < 192) g_bias_oa[tid] = boff[tid];
        if (tid < 96)  g_bias_oa[192 + tid] = batt[tid];
        return;
    }
    const float* W; __nv_bfloat16* Wt; int K, N, tile;
    if (b < 64)       { W = Wv;   Wt = w_v;            K = 256;  N = 256;  tile = b; }
    else if (b < 112) { W = Woff; Wt = w_oa;           K = 256;  N = 192;  tile = b - 64; }
    else if (b < 136) { W = Wat;  Wt = w_oa + 192*256; K = 256;  N = 96;   tile = b - 112; }
    else if (b < 200) { W = Wout; Wt = w_outm;         K = 256;  N = 256;  tile = b - 136; }
    else if (b < 456) { W = Wf1;  Wt = w_f1;           K = 256;  N = 1024; tile = b - 200; }
    else              { W = Wf2;  Wt = w_f2;           K = 1024; N = 256;  tile = b - 456; }
    const int tn = N >> 5;
    const int nb = (tile % tn) * 32, kb = (tile / tn) * 32;
    const int tx = threadIdx.x, ty = threadIdx.y;   // (32, 8)
    #pragma unroll
    for (int r = 0; r < 4; r++)
        t[ty + r * 8][tx] = W[(size_t)(kb + ty + r * 8) * N + nb + tx];
    __syncthreads();
    #pragma unroll
    for (int r = 0; r < 4; r++)
        Wt[(size_t)(nb + ty + r * 8) * K + kb + tx] =
            __float2bfloat16_rn(t[tx][ty + r * 8]);
}

// ---------------- LayerNorm standalone (LN2) ------------------------------------
template<int INID, int OUT16>
__global__ void __launch_bounds__(256) ln_kernel(const float* __restrict__ gam,
                                                 const float* __restrict__ bet)
{
    __shared__ float red[8];
    __shared__ float s_mean, s_var;
    ln_row(gbuf<INID>(), gam, bet, nullptr, gb16<OUT16>(), red, &s_mean, &s_var,
           blockIdx.x, threadIdx.x);
}

// ---------------- bf16 tensor-core GEMM, 3-stage cp.async + ldmatrix ------------
template<int EPI, int A16, int WID, int BID, int RID, int CID, int C16>
__global__ void __launch_bounds__(256, 2) tgemm(const float* __restrict__ bias_ext,
                                                const float* __restrict__ res_ext,
                                                float* __restrict__ C_ext,
                                                int M, int N, int K)
{
    const __nv_bfloat16* A  = gb16<A16>();
    const __nv_bfloat16* Wt = gw16<WID>();
    const float* bias = (BID == 0) ? bias_ext : g_bias_oa;
    const float* res  = (RID == 0) ? res_ext  : gbuf<RID>();

    __shared__ uint32_t As[3][128 * 16];
    __shared__ uint32_t Bs[3][128 * 16];

    const int tid  = threadIdx.x;
    const int warp = tid >> 5;
    const int lane = tid & 31;
    const int g    = lane >> 2;
    const int tg   = lane & 3;
    const int mw   = (warp & 1) * 64;
    const int nw   = (warp >> 1) * 32;
    const int m0   = blockIdx.y * 128;
    const int n0   = blockIdx.x * 128;

    const int arow = mw + (lane & 7) + (((lane >> 3) & 1) << 3);
    const int acs  = lane >> 4;
    const int brow = nw + (lane & 7);
    const int bcs  = (lane >> 3) & 1;

    int rr[2], sw[2], c8[2];
    #pragma unroll
    for (int i = 0; i < 2; i++) {
        int idx = tid + i * 256;
        int r = idx >> 2, c = idx & 3;
        rr[i] = r;
        c8[i] = c * 8;
        sw[i] = r * 16 + ((c ^ ((r >> 1) & 3)) << 2);
    }

    auto prefetch = [&](int tile, int buf) {
        const int k0 = tile << 5;
        #pragma unroll
        for (int i = 0; i < 2; i++) {
            uint32_t sa = (uint32_t)__cvta_generic_to_shared(&As[buf][sw[i]]);
            const __nv_bfloat16* gp = A + (size_t)(m0 + rr[i]) * K + k0 + c8[i];
            int sz = (m0 + rr[i] < M) ? 16 : 0;
            asm volatile("cp.async.cg.shared.global [%0], [%1], 16, %2;"
                         :: "r"(sa), "l"(gp), "r"(sz));
        }
        #pragma unroll
        for (int i = 0; i < 2; i++) {
            uint32_t sa = (uint32_t)__cvta_generic_to_shared(&Bs[buf][sw[i]]);
            const __nv_bfloat16* gp = Wt + (size_t)(n0 + rr[i]) * K + k0 + c8[i];
            int sz = (n0 + rr[i] < N) ? 16 : 0;
            asm volatile("cp.async.cg.shared.global [%0], [%1], 16, %2;"
                         :: "r"(sa), "l"(gp), "r"(sz));
        }
        asm volatile("cp.async.commit_group;");
    };

    float c[4][4][4];
    #pragma unroll
    for (int mt = 0; mt < 4; mt++)
        #pragma unroll
        for (int nt = 0; nt < 4; nt++)
            #pragma unroll
            for (int r = 0; r < 4; r++) c[mt][nt][r] = 0.f;

    const uint32_t abase0 = (uint32_t)__cvta_generic_to_shared(&As[0][0]);
    const uint32_t bbase0 = (uint32_t)__cvta_generic_to_shared(&Bs[0][0]);

    const int T = K >> 5;
    prefetch(0, 0);
    prefetch(1, 1);

    int buf = 0;
    for (int t = 0; t < T; t++) {
        asm volatile("cp.async.wait_group 1;");
        __syncthreads();
        if (t + 2 < T) prefetch(t + 2, (buf + 2) % 3);

        const uint32_t abase = abase0 + buf * 8192;
        const uint32_t bbase = bbase0 + buf * 8192;
        #pragma unroll
        for (int ks = 0; ks < 2; ks++) {
            uint32_t a[4][4], b[4][2];
            #pragma unroll
            for (int mt = 0; mt < 4; mt++) {
                const int r = arow + mt * 16;
                const int cch = ks * 2 + acs;
                const uint32_t ad = abase + 64 * r + 16 * (cch ^ ((r >> 1) & 3));
                asm volatile(
                    "ldmatrix.sync.aligned.m8n8.x4.shared.b16 {%0,%1,%2,%3}, [%4];"
                    : "=r"(a[mt][0]), "=r"(a[mt][1]), "=r"(a[mt][2]), "=r"(a[mt][3])
                    : "r"(ad));
            }
            #pragma unroll
            for (int nt = 0; nt < 4; nt++) {
                const int r = brow + nt * 8;
                const int cch = ks * 2 + bcs;
                const uint32_t bd = bbase + 64 * r + 16 * (cch ^ ((r >> 1) & 3));
                asm volatile(
                    "ldmatrix.sync.aligned.m8n8.x2.shared.b16 {%0,%1}, [%2];"
                    : "=r"(b[nt][0]), "=r"(b[nt][1])
                    : "r"(bd));
            }
            #pragma unroll
            for (int mt = 0; mt < 4; mt++)
                #pragma unroll
                for (int nt = 0; nt < 4; nt++) {
                    asm volatile(
                        "mma.sync.aligned.m16n8k16.row.col.f32.bf16.bf16.f32 "
                        "{%0,%1,%2,%3}, {%4,%5,%6,%7}, {%8,%9}, {%0,%1,%2,%3};"
                        : "+f"(c[mt][nt][0]), "+f"(c[mt][nt][1]),
                          "+f"(c[mt][nt][2]), "+f"(c[mt][nt][3])
                        : "r"(a[mt][0]), "r"(a[mt][1]), "r"(a[mt][2]), "r"(a[mt][3]),
                          "r"(b[nt][0]), "r"(b[nt][1]));
                }
        }
        buf = (buf + 1) % 3;
    }

    // --- epilogue: packed pair stores (cn even; N even -> cn+1 in range) ---
    #pragma unroll
    for (int mt = 0; mt < 4; mt++) {
        #pragma unroll
        for (int nt = 0; nt < 4; nt++) {
            const int cn = n0 + nw + nt * 8 + 2 * tg;
            if (cn >= N) continue;
            const float2 bia = *(const float2*)(bias + cn);
            #pragma unroll
            for (int half = 0; half < 2; half++) {
                const int rm = m0 + mw + mt * 16 + g + half * 8;
                if (rm >= M) continue;
                float v0 = c[mt][nt][half * 2 + 0] + bia.x;
                float v1 = c[mt][nt][half * 2 + 1] + bia.y;
                if (EPI == 1) {
                    const float2 rv = *(const float2*)(res + (size_t)rm * N + cn);
                    v0 += rv.x; v1 += rv.y;
                }
                if (EPI == 2) {
                    v0 = 0.5f * v0 * (1.0f + erff(v0 * 0.70710678118654752440f));
                    v1 = 0.5f * v1 * (1.0f + erff(v1 * 0.70710678118654752440f));
                }
                if (C16 != 0) {
                    __nv_bfloat162 p;
                    p.x = __float2bfloat16_rn(v0);
                    p.y = __float2bfloat16_rn(v1);
                    *(__nv_bfloat162*)(gb16<C16>() + (size_t)rm * N + cn) = p;
                } else {
                    float* C = (CID == 0) ? C_ext : gbuf<CID>();
                    *(float2*)(C + (size_t)rm * N + cn) = make_float2(v0, v1);
                }
            }
        }
    }
}

// ---------------- fused softmax + deformable bilinear sampling ------------------
// Branch-free clamped gathers: weight *= validity, index clamped in-range.
// All 48 loads per warp are unconditional -> high MLP.
__global__ void __launch_bounds__(256) deform_kernel(const float* __restrict__ refp)
{
    const __nv_bfloat16* v = b_vout;
    const float* oa = g_oa;

    const int w = blockIdx.x * 8 + (threadIdx.x >> 5);
    const int lane = threadIdx.x & 31;
    const int h  = w & 7;
    const int bq = w >> 3;
    const int b  = bq >> 14;

    const float rx = refp[bq * 2 + 0];
    const float ry = refp[bq * 2 + 1];
    const float* off_p  = oa + (size_t)bq * 288 + h * 24;
    const float* attn_p = oa + (size_t)bq * 288 + 192 + h * 12;

    float lg[12];
    float mx = -1e30f;
    #pragma unroll
    for (int j = 0; j < 12; j++) { lg[j] = attn_p[j]; mx = fmaxf(mx, lg[j]); }
    float ssum = 0.f;
    #pragma unroll
    for (int j = 0; j < 12; j++) { lg[j] = expf(lg[j] - mx); ssum += lg[j]; }
    const float inv = 1.0f / ssum;

    const int Hls[3] = {100, 50, 25};
    const int Wls[3] = {100, 50, 25};
    const int st [3] = {0, 10000, 12500};

    float acc = 0.f;
    #pragma unroll
    for (int l = 0; l < NLVL; l++) {
        const int Hl = Hls[l], Wl = Wls[l];
        const float fW = (float)Wl, fH = (float)Hl;
        const size_t vbase = ((size_t)b * NV + st[l]) * CDIM + h * HDIM + lane;
        #pragma unroll
        for (int p = 0; p < NPT; p++) {
            const int j = l * 4 + p;
            const float ox = off_p[2 * j], oy = off_p[2 * j + 1];
            const float locx = rx + ox / fW;
            const float locy = ry + oy / fH;
            const float x = locx * fW - 0.5f;
            const float y = locy * fH - 0.5f;
            const float x0f = floorf(x), y0f = floorf(y);
            const float lx = x - x0f, ly = y - y0f;
            const int x0 = (int)x0f, y0 = (int)y0f;
            const int x1 = x0 + 1, y1 = y0 + 1;

            const bool vx0 = (x0 >= 0) & (x0 < Wl);
            const bool vx1 = (x1 >= 0) & (x1 < Wl);
            const bool vy0 = (y0 >= 0) & (y0 < Hl);
            const bool vy1 = (y1 >= 0) & (y1 < Hl);
            const float w00 = (vx0 & vy0) ? (1.f - lx) * (1.f - ly) : 0.f;
            const float w01 = (vx1 & vy0) ? lx * (1.f - ly) : 0.f;
            const float w10 = (vx0 & vy1) ? (1.f - lx) * ly : 0.f;
            const float w11 = (vx1 & vy1) ? lx * ly : 0.f;

            const int cx0 = min(max(x0, 0), Wl - 1);
            const int cx1 = min(max(x1, 0), Wl - 1);
            const int cy0 = min(max(y0, 0), Hl - 1);
            const int cy1 = min(max(y1, 0), Hl - 1);

            // unconditional, batchable gathers
            const float s00 = __bfloat162float(v[vbase + (size_t)(cy0 * Wl + cx0) * CDIM]);
            const float s01 = __bfloat162float(v[vbase + (size_t)(cy0 * Wl + cx1) * CDIM]);
            const float s10 = __bfloat162float(v[vbase + (size_t)(cy1 * Wl + cx0) * CDIM]);
            const float s11 = __bfloat162float(v[vbase + (size_t)(cy1 * Wl + cx1) * CDIM]);

            const float smp = w00 * s00 + w01 * s01 + w10 * s10 + w11 * s11;
            acc = fmaf(lg[j] * inv, smp, acc);
        }
    }
    b_samp[(size_t)bq * CDIM + h * HDIM + lane] = __float2bfloat16_rn(acc);
}

// ---------------- launch --------------------------------------------------------
extern "C" void kernel_launch(void* const* d_in, const int* in_sizes, int n_in,
                              void* d_out, int out_size)
{
    const float* query     = (const float*)d_in[0];
    const float* value     = (const float*)d_in[1];
    const float* query_pos = (const float*)d_in[2];
    const float* ref_pts   = (const float*)d_in[3];
    const float* ln1_g = (const float*)d_in[6];
    const float* ln1_b = (const float*)d_in[7];
    const float* ln2_g = (const float*)d_in[8];
    const float* ln2_b = (const float*)d_in[9];
    const float* W_value = (const float*)d_in[10];
    const float* b_value = (const float*)d_in[11];
    const float* W_off   = (const float*)d_in[12];
    const float* b_off   = (const float*)d_in[13];
    const float* W_attn  = (const float*)d_in[14];
    const float* b_attn  = (const float*)d_in[15];
    const float* W_out   = (const float*)d_in[16];
    const float* b_out   = (const float*)d_in[17];
    const float* W_ffn1  = (const float*)d_in[18];
    const float* b_ffn1  = (const float*)d_in[19];
    const float* W_ffn2  = (const float*)d_in[20];
    const float* b_ffn2  = (const float*)d_in[21];
    float* out = (float*)d_out;

    // 0) mega pre-pass: weight transposes + bias concat + value cvt + LN1
    prepass_all<<<LN1_BASE + BQ, dim3(32, 8)>>>(
        W_value, W_off, W_attn, W_out, W_ffn1, W_ffn2, b_off, b_attn,
        value, query, query_pos, ln1_g, ln1_b);

    // 1) b_vout = bf16(b_vin @ w_v^T + b_value)
    tgemm<0, 2, 1, 0, 0, 0, 6><<<dim3(2, (BNV + 127) / 128), 256>>>(
        b_value, nullptr, nullptr, BNV, CDIM, CDIM);
    // 2) g_oa = b_q @ w_oa^T + bias_oa   (fused offset+attn, N=288)
    tgemm<0, 1, 2, 1, 0, 1, 0><<<dim3(3, BQ / 128), 256>>>(
        nullptr, nullptr, nullptr, BQ, 288, CDIM);
    // 3) deform -> b_samp
    deform_kernel<<<(BQ * NHEAD) / 8, 256>>>(ref_pts);
    // 4) g_x = query + b_samp @ w_outm^T + b_out
    tgemm<1, 3, 3, 0, 0, 2, 0><<<dim3(2, BQ / 128), 256>>>(
        b_out, query, nullptr, BQ, CDIM, CDIM);
    // 5) b_h = bf16(LN2(g_x))
    ln_kernel<2, 4><<<BQ, 256>>>(ln2_g, ln2_b);
    // 6) b_ffn = bf16(gelu(b_h @ w_f1^T + b_ffn1))
    tgemm<2, 4, 4, 0, 0, 0, 5><<<dim3(8, BQ / 128), 256>>>(
        b_ffn1, nullptr, nullptr, BQ, FDIM, CDIM);
    // 7) out = g_x + b_ffn @ w_f2^T + b_ffn2
    tgemm<1, 5, 5, 0, 2, 0, 0><<<dim3(2, BQ / 128), 256>>>(
        b_ffn2, nullptr, out, BQ, CDIM, FDIM);
}

// round 17
// speedup vs baseline: 1.4878x; 1.4878x over previous
#include <cuda_runtime.h>
#include <cuda_bf16.h>
#include <math.h>
#include <stdint.h>

// ---------------- problem constants ----------------
#define BATCH 2
#define QN    16384
#define CDIM  256
#define NHEAD 8
#define HDIM  32
#define NLVL  3
#define NPT   4
#define NV    13125
#define FDIM  1024
#define BQ    (BATCH*QN)       // 32768
#define BNV   (BATCH*NV)       // 26250

// ---------------- fp32 scratch ----------------
__device__ float g_oa  [BQ * 288];      // 1: fused offset(192)+attn(96) logits
__device__ float g_x   [BQ * CDIM];     // 2: post-attn residual
__device__ float g_bias_oa[288];        // concat bias for fused GEMM

// ---------------- bf16 activation scratch ----------------
__device__ __nv_bfloat16 b_q   [BQ * CDIM];    // 1: LN1+pos
__device__ __nv_bfloat16 b_vin [BNV * CDIM];   // 2: value (pre-rounded)
__device__ __nv_bfloat16 b_samp[BQ * CDIM];    // 3: deform out
__device__ __nv_bfloat16 b_h   [BQ * CDIM];    // 4: LN2 out
__device__ __nv_bfloat16 b_ffn [BQ * FDIM];    // 5: FFN hidden
__device__ __nv_bfloat16 b_vout[BNV * CDIM];   // 6: value projection (deform reads)

// ---------------- bf16 transposed weights [n][k] ----------------
__device__ __nv_bfloat16 w_v   [CDIM * CDIM];  // 1
__device__ __nv_bfloat16 w_oa  [288  * CDIM];  // 2 (rows 0..191 off, 192..287 attn)
__device__ __nv_bfloat16 w_outm[CDIM * CDIM];  // 3
__device__ __nv_bfloat16 w_f1  [FDIM * CDIM];  // 4
__device__ __nv_bfloat16 w_f2  [CDIM * FDIM];  // 5

template<int ID> __device__ __forceinline__ float* gbuf() {
    if constexpr (ID == 1) return g_oa;
    else if constexpr (ID == 2) return g_x;
    else return nullptr;
}
template<int ID> __device__ __forceinline__ __nv_bfloat16* gb16() {
    if constexpr (ID == 1) return b_q;
    else if constexpr (ID == 2) return b_vin;
    else if constexpr (ID == 3) return b_samp;
    else if constexpr (ID == 4) return b_h;
    else if constexpr (ID == 5) return b_ffn;
    else if constexpr (ID == 6) return b_vout;
    else return nullptr;
}
template<int ID> __device__ __forceinline__ __nv_bfloat16* gw16() {
    if constexpr (ID == 1) return w_v;
    else if constexpr (ID == 2) return w_oa;
    else if constexpr (ID == 3) return w_outm;
    else if constexpr (ID == 4) return w_f1;
    else if constexpr (ID == 5) return w_f2;
    else return nullptr;
}

// ---------------- shared LayerNorm row routine (256 threads per row) ------------
__device__ __forceinline__ void ln_row(const float* __restrict__ in,
                                       const float* __restrict__ gam,
                                       const float* __restrict__ bet,
                                       const float* __restrict__ add,
                                       __nv_bfloat16* __restrict__ out,
                                       float* red, float* s_mean, float* s_var,
                                       int row, int t)
{
    const size_t base = (size_t)row * CDIM;
    float x = in[base + t];

    float s = x;
    #pragma unroll
    for (int o = 16; o > 0; o >>= 1) s += __shfl_xor_sync(0xffffffffu, s, o);
    if ((t & 31) == 0) red[t >> 5] = s;
    __syncthreads();
    if (t < 32) {
        float v = (t < 8) ? red[t] : 0.f;
        #pragma unroll
        for (int o = 4; o > 0; o >>= 1) v += __shfl_xor_sync(0xffffffffu, v, o);
        if (t == 0) *s_mean = v * (1.0f / CDIM);
    }
    __syncthreads();
    const float mean = *s_mean;
    float dx = x - mean;

    float s2 = dx * dx;
    #pragma unroll
    for (int o = 16; o > 0; o >>= 1) s2 += __shfl_xor_sync(0xffffffffu, s2, o);
    __syncthreads();
    if ((t & 31) == 0) red[t >> 5] = s2;
    __syncthreads();
    if (t < 32) {
        float v = (t < 8) ? red[t] : 0.f;
        #pragma unroll
        for (int o = 4; o > 0; o >>= 1) v += __shfl_xor_sync(0xffffffffu, v, o);
        if (t == 0) *s_var = v * (1.0f / CDIM);
    }
    __syncthreads();
    float y = dx * rsqrtf(*s_var + 1e-5f) * gam[t] + bet[t];
    if (add) y += add[base + t];
    out[base + t] = __float2bfloat16_rn(y);
}

// ---------------- mega pre-pass: transposes + bias concat + value cvt + LN1 -----
#define CVT_BLKS 6563
#define LN1_BASE (713 + CVT_BLKS)
__global__ void __launch_bounds__(256) prepass_all(
    const float* __restrict__ Wv,  const float* __restrict__ Woff,
    const float* __restrict__ Wat, const float* __restrict__ Wout,
    const float* __restrict__ Wf1, const float* __restrict__ Wf2,
    const float* __restrict__ boff, const float* __restrict__ batt,
    const float* __restrict__ value,
    const float* __restrict__ query, const float* __restrict__ qpos,
    const float* __restrict__ ln1g, const float* __restrict__ ln1b)
{
    __shared__ float t[32][33];
    const int b = blockIdx.x;
    const int tid = threadIdx.y * 32 + threadIdx.x;

    if (b >= LN1_BASE) {                  // LN1 rows
        __shared__ float red[8];
        __shared__ float s_mean, s_var;
        ln_row(query, ln1g, ln1b, qpos, b_q, red, &s_mean, &s_var,
               b - LN1_BASE, tid);
        return;
    }
    if (b >= 713) {                       // value fp32 -> bf16
        const size_t i = ((size_t)(b - 713) * 256 + tid) * 4;
        if (i + 3 < (size_t)BNV * CDIM) {
            float4 v = *(const float4*)(value + i);
            b_vin[i + 0] = __float2bfloat16_rn(v.x);
            b_vin[i + 1] = __float2bfloat16_rn(v.y);
            b_vin[i + 2] = __float2bfloat16_rn(v.z);
            b_vin[i + 3] = __float2bfloat16_rn(v.w);
        }
        return;
    }
    if (b == 712) {                       // bias concat
        if (tid < 192) g_bias_oa[tid] = boff[tid];
        if (tid < 96)  g_bias_oa[192 + tid] = batt[tid];
        return;
    }
    const float* W; __nv_bfloat16* Wt; int K, N, tile;
    if (b < 64)       { W = Wv;   Wt = w_v;            K = 256;  N = 256;  tile = b; }
    else if (b < 112) { W = Woff; Wt = w_oa;           K = 256;  N = 192;  tile = b - 64; }
    else if (b < 136) { W = Wat;  Wt = w_oa + 192*256; K = 256;  N = 96;   tile = b - 112; }
    else if (b < 200) { W = Wout; Wt = w_outm;         K = 256;  N = 256;  tile = b - 136; }
    else if (b < 456) { W = Wf1;  Wt = w_f1;           K = 256;  N = 1024; tile = b - 200; }
    else              { W = Wf2;  Wt = w_f2;           K = 1024; N = 256;  tile = b - 456; }
    const int tn = N >> 5;
    const int nb = (tile % tn) * 32, kb = (tile / tn) * 32;
    const int tx = threadIdx.x, ty = threadIdx.y;   // (32, 8)
    #pragma unroll
    for (int r = 0; r < 4; r++)
        t[ty + r * 8][tx] = W[(size_t)(kb + ty + r * 8) * N + nb + tx];
    __syncthreads();
    #pragma unroll
    for (int r = 0; r < 4; r++)
        Wt[(size_t)(nb + ty + r * 8) * K + kb + tx] =
            __float2bfloat16_rn(t[tx][ty + r * 8]);
}

// ---------------- LayerNorm standalone (LN2) ------------------------------------
template<int INID, int OUT16>
__global__ void __launch_bounds__(256) ln_kernel(const float* __restrict__ gam,
                                                 const float* __restrict__ bet)
{
    __shared__ float red[8];
    __shared__ float s_mean, s_var;
    ln_row(gbuf<INID>(), gam, bet, nullptr, gb16<OUT16>(), red, &s_mean, &s_var,
           blockIdx.x, threadIdx.x);
}

// ---------------- bf16 tensor-core GEMM, 3-stage cp.async + ldmatrix ------------
template<int EPI, int A16, int WID, int BID, int RID, int CID, int C16>
__global__ void __launch_bounds__(256, 2) tgemm(const float* __restrict__ bias_ext,
                                                const float* __restrict__ res_ext,
                                                float* __restrict__ C_ext,
                                                int M, int N, int K)
{
    const __nv_bfloat16* A  = gb16<A16>();
    const __nv_bfloat16* Wt = gw16<WID>();
    const float* bias = (BID == 0) ? bias_ext : g_bias_oa;
    const float* res  = (RID == 0) ? res_ext  : gbuf<RID>();

    __shared__ uint32_t As[3][128 * 16];
    __shared__ uint32_t Bs[3][128 * 16];

    const int tid  = threadIdx.x;
    const int warp = tid >> 5;
    const int lane = tid & 31;
    const int g    = lane >> 2;
    const int tg   = lane & 3;
    const int mw   = (warp & 1) * 64;
    const int nw   = (warp >> 1) * 32;
    const int m0   = blockIdx.y * 128;
    const int n0   = blockIdx.x * 128;

    const int arow = mw + (lane & 7) + (((lane >> 3) & 1) << 3);
    const int acs  = lane >> 4;
    const int brow = nw + (lane & 7);
    const int bcs  = (lane >> 3) & 1;

    int rr[2], sw[2], c8[2];
    #pragma unroll
    for (int i = 0; i < 2; i++) {
        int idx = tid + i * 256;
        int r = idx >> 2, c = idx & 3;
        rr[i] = r;
        c8[i] = c * 8;
        sw[i] = r * 16 + ((c ^ ((r >> 1) & 3)) << 2);
    }

    auto prefetch = [&](int tile, int buf) {
        const int k0 = tile << 5;
        #pragma unroll
        for (int i = 0; i < 2; i++) {
            uint32_t sa = (uint32_t)__cvta_generic_to_shared(&As[buf][sw[i]]);
            const __nv_bfloat16* gp = A + (size_t)(m0 + rr[i]) * K + k0 + c8[i];
            int sz = (m0 + rr[i] < M) ? 16 : 0;
            asm volatile("cp.async.cg.shared.global [%0], [%1], 16, %2;"
                         :: "r"(sa), "l"(gp), "r"(sz));
        }
        #pragma unroll
        for (int i = 0; i < 2; i++) {
            uint32_t sa = (uint32_t)__cvta_generic_to_shared(&Bs[buf][sw[i]]);
            const __nv_bfloat16* gp = Wt + (size_t)(n0 + rr[i]) * K + k0 + c8[i];
            int sz = (n0 + rr[i] < N) ? 16 : 0;
            asm volatile("cp.async.cg.shared.global [%0], [%1], 16, %2;"
                         :: "r"(sa), "l"(gp), "r"(sz));
        }
        asm volatile("cp.async.commit_group;");
    };

    float c[4][4][4];
    #pragma unroll
    for (int mt = 0; mt < 4; mt++)
        #pragma unroll
        for (int nt = 0; nt < 4; nt++)
            #pragma unroll
            for (int r = 0; r < 4; r++) c[mt][nt][r] = 0.f;

    const uint32_t abase0 = (uint32_t)__cvta_generic_to_shared(&As[0][0]);
    const uint32_t bbase0 = (uint32_t)__cvta_generic_to_shared(&Bs[0][0]);

    const int T = K >> 5;
    prefetch(0, 0);
    prefetch(1, 1);

    int buf = 0;
    for (int t = 0; t < T; t++) {
        asm volatile("cp.async.wait_group 1;");
        __syncthreads();
        if (t + 2 < T) prefetch(t + 2, (buf + 2) % 3);

        const uint32_t abase = abase0 + buf * 8192;
        const uint32_t bbase = bbase0 + buf * 8192;
        #pragma unroll
        for (int ks = 0; ks < 2; ks++) {
            uint32_t a[4][4], b[4][2];
            #pragma unroll
            for (int mt = 0; mt < 4; mt++) {
                const int r = arow + mt * 16;
                const int cch = ks * 2 + acs;
                const uint32_t ad = abase + 64 * r + 16 * (cch ^ ((r >> 1) & 3));
                asm volatile(
                    "ldmatrix.sync.aligned.m8n8.x4.shared.b16 {%0,%1,%2,%3}, [%4];"
                    : "=r"(a[mt][0]), "=r"(a[mt][1]), "=r"(a[mt][2]), "=r"(a[mt][3])
                    : "r"(ad));
            }
            #pragma unroll
            for (int nt = 0; nt < 4; nt++) {
                const int r = brow + nt * 8;
                const int cch = ks * 2 + bcs;
                const uint32_t bd = bbase + 64 * r + 16 * (cch ^ ((r >> 1) & 3));
                asm volatile(
                    "ldmatrix.sync.aligned.m8n8.x2.shared.b16 {%0,%1}, [%2];"
                    : "=r"(b[nt][0]), "=r"(b[nt][1])
                    : "r"(bd));
            }
            #pragma unroll
            for (int mt = 0; mt < 4; mt++)
                #pragma unroll
                for (int nt = 0; nt < 4; nt++) {
                    asm volatile(
                        "mma.sync.aligned.m16n8k16.row.col.f32.bf16.bf16.f32 "
                        "{%0,%1,%2,%3}, {%4,%5,%6,%7}, {%8,%9}, {%0,%1,%2,%3};"
                        : "+f"(c[mt][nt][0]), "+f"(c[mt][nt][1]),
                          "+f"(c[mt][nt][2]), "+f"(c[mt][nt][3])
                        : "r"(a[mt][0]), "r"(a[mt][1]), "r"(a[mt][2]), "r"(a[mt][3]),
                          "r"(b[nt][0]), "r"(b[nt][1]));
                }
        }
        buf = (buf + 1) % 3;
    }

    // --- epilogue: packed pair stores ---
    #pragma unroll
    for (int mt = 0; mt < 4; mt++) {
        #pragma unroll
        for (int nt = 0; nt < 4; nt++) {
            const int cn = n0 + nw + nt * 8 + 2 * tg;
            if (cn >= N) continue;
            const float2 bia = *(const float2*)(bias + cn);
            #pragma unroll
            for (int half = 0; half < 2; half++) {
                const int rm = m0 + mw + mt * 16 + g + half * 8;
                if (rm >= M) continue;
                float v0 = c[mt][nt][half * 2 + 0] + bia.x;
                float v1 = c[mt][nt][half * 2 + 1] + bia.y;
                if (EPI == 1) {
                    const float2 rv = *(const float2*)(res + (size_t)rm * N + cn);
                    v0 += rv.x; v1 += rv.y;
                }
                if (EPI == 2) {
                    v0 = 0.5f * v0 * (1.0f + erff(v0 * 0.70710678118654752440f));
                    v1 = 0.5f * v1 * (1.0f + erff(v1 * 0.70710678118654752440f));
                }
                if (C16 != 0) {
                    __nv_bfloat162 p;
                    p.x = __float2bfloat16_rn(v0);
                    p.y = __float2bfloat16_rn(v1);
                    *(__nv_bfloat162*)(gb16<C16>() + (size_t)rm * N + cn) = p;
                } else {
                    float* C = (CID == 0) ? C_ext : gbuf<CID>();
                    *(float2*)(C + (size_t)rm * N + cn) = make_float2(v0, v1);
                }
            }
        }
    }
}

// ---------------- fused softmax + deformable bilinear sampling ------------------
// Warp-offloaded scalars: lane j<12 computes point j's softmax-weighted bilinear
// weights + clamped base index + deltas ONCE; gather loop broadcasts via shfl.
__global__ void __launch_bounds__(256) deform_kernel(const float* __restrict__ refp)
{
    const int w = blockIdx.x * 8 + (threadIdx.x >> 5);
    const int lane = threadIdx.x & 31;
    const int h  = w & 7;
    const int bq = w >> 3;
    const int b  = bq >> 14;

    const float* off_p  = g_oa + (size_t)bq * 288 + h * 24;
    const float* attn_p = g_oa + (size_t)bq * 288 + 192 + h * 12;

    // softmax over 12 logits via warp reductions (lanes >=12 contribute identity)
    float lgj = (lane < 12) ? attn_p[lane] : -1e30f;
    float mx = lgj;
    #pragma unroll
    for (int o = 16; o > 0; o >>= 1) mx = fmaxf(mx, __shfl_xor_sync(0xffffffffu, mx, o));
    float ej = (lane < 12) ? expf(lgj - mx) : 0.f;
    float ssum = ej;
    #pragma unroll
    for (int o = 16; o > 0; o >>= 1) ssum += __shfl_xor_sync(0xffffffffu, ssum, o);
    const float inv = 1.0f / ssum;

    // per-point data on lane j
    int i00 = 0, dxi = 0, dyi = 0;
    float pw00 = 0.f, pw01 = 0.f, pw10 = 0.f, pw11 = 0.f;
    if (lane < 12) {
        const int l   = lane >> 2;
        const int Wl  = (l == 0) ? 100 : (l == 1) ? 50 : 25;
        const int stl = (l == 0) ? 0 : (l == 1) ? 10000 : 12500;
        const float fW = (float)Wl;
        const float rx = refp[bq * 2 + 0];
        const float ry = refp[bq * 2 + 1];
        const float ox = off_p[2 * lane], oy = off_p[2 * lane + 1];
        // (rx + ox/W)*W - 0.5 == rx*W + ox - 0.5
        const float x = fmaf(rx, fW, ox) - 0.5f;
        const float y = fmaf(ry, fW, oy) - 0.5f;
        const float x0f = floorf(x), y0f = floorf(y);
        const float lx = x - x0f, ly = y - y0f;
        const int x0 = (int)x0f, y0 = (int)y0f;
        const int x1 = x0 + 1, y1 = y0 + 1;
        const bool vx0 = (x0 >= 0) & (x0 < Wl);
        const bool vx1 = (x1 >= 0) & (x1 < Wl);
        const bool vy0 = (y0 >= 0) & (y0 < Wl);
        const bool vy1 = (y1 >= 0) & (y1 < Wl);
        const float sw = ej * inv;
        pw00 = (vx0 & vy0) ? sw * (1.f - lx) * (1.f - ly) : 0.f;
        pw01 = (vx1 & vy0) ? sw * lx * (1.f - ly) : 0.f;
        pw10 = (vx0 & vy1) ? sw * (1.f - lx) * ly : 0.f;
        pw11 = (vx1 & vy1) ? sw * lx * ly : 0.f;
        const int cx0 = min(max(x0, 0), Wl - 1);
        const int cx1 = min(max(x1, 0), Wl - 1);
        const int cy0 = min(max(y0, 0), Wl - 1);
        const int cy1 = min(max(y1, 0), Wl - 1);
        i00 = (stl + cy0 * Wl + cx0) * CDIM;
        dxi = (cx1 - cx0) * CDIM;
        dyi = (cy1 - cy0) * Wl * CDIM;
    }

    const __nv_bfloat16* vb = b_vout + (size_t)b * NV * CDIM + h * HDIM + lane;
    float acc = 0.f;
    #pragma unroll
    for (int j = 0; j < 12; j++) {
        const int   k00 = __shfl_sync(0xffffffffu, i00, j);
        const int   kdx = __shfl_sync(0xffffffffu, dxi, j);
        const int   kdy = __shfl_sync(0xffffffffu, dyi, j);
        const float q00 = __shfl_sync(0xffffffffu, pw00, j);
        const float q01 = __shfl_sync(0xffffffffu, pw01, j);
        const float q10 = __shfl_sync(0xffffffffu, pw10, j);
        const float q11 = __shfl_sync(0xffffffffu, pw11, j);
        const float s00 = __bfloat162float(vb[k00]);
        const float s01 = __bfloat162float(vb[k00 + kdx]);
        const float s10 = __bfloat162float(vb[k00 + kdy]);
        const float s11 = __bfloat162float(vb[k00 + kdx + kdy]);
        acc = fmaf(q00, s00, acc);
        acc = fmaf(q01, s01, acc);
        acc = fmaf(q10, s10, acc);
        acc = fmaf(q11, s11, acc);
    }
    b_samp[(size_t)bq * CDIM + h * HDIM + lane] = __float2bfloat16_rn(acc);
}

// ---------------- launch --------------------------------------------------------
extern "C" void kernel_launch(void* const* d_in, const int* in_sizes, int n_in,
                              void* d_out, int out_size)
{
    const float* query     = (const float*)d_in[0];
    const float* value     = (const float*)d_in[1];
    const float* query_pos = (const float*)d_in[2];
    const float* ref_pts   = (const float*)d_in[3];
    const float* ln1_g = (const float*)d_in[6];
    const float* ln1_b = (const float*)d_in[7];
    const float* ln2_g = (const float*)d_in[8];
    const float* ln2_b = (const float*)d_in[9];
    const float* W_value = (const float*)d_in[10];
    const float* b_value = (const float*)d_in[11];
    const float* W_off   = (const float*)d_in[12];
    const float* b_off   = (const float*)d_in[13];
    const float* W_attn  = (const float*)d_in[14];
    const float* b_attn  = (const float*)d_in[15];
    const float* W_out   = (const float*)d_in[16];
    const float* b_out   = (const float*)d_in[17];
    const float* W_ffn1  = (const float*)d_in[18];
    const float* b_ffn1  = (const float*)d_in[19];
    const float* W_ffn2  = (const float*)d_in[20];
    const float* b_ffn2  = (const float*)d_in[21];
    float* out = (float*)d_out;

    // 0) mega pre-pass: weight transposes + bias concat + value cvt + LN1
    prepass_all<<<LN1_BASE + BQ, dim3(32, 8)>>>(
        W_value, W_off, W_attn, W_out, W_ffn1, W_ffn2, b_off, b_attn,
        value, query, query_pos, ln1_g, ln1_b);

    // 1) b_vout = bf16(b_vin @ w_v^T + b_value)
    tgemm<0, 2, 1, 0, 0, 0, 6><<<dim3(2, (BNV + 127) / 128), 256>>>(
        b_value, nullptr, nullptr, BNV, CDIM, CDIM);
    // 2) g_oa = b_q @ w_oa^T + bias_oa   (fused offset+attn, N=288)
    tgemm<0, 1, 2, 1, 0, 1, 0><<<dim3(3, BQ / 128), 256>>>(
        nullptr, nullptr, nullptr, BQ, 288, CDIM);
    // 3) deform -> b_samp
    deform_kernel<<<(BQ * NHEAD) / 8, 256>>>(ref_pts);
    // 4) g_x = query + b_samp @ w_outm^T + b_out
    tgemm<1, 3, 3, 0, 0, 2, 0><<<dim3(2, BQ / 128), 256>>>(
        b_out, query, nullptr, BQ, CDIM, CDIM);
    // 5) b_h = bf16(LN2(g_x))
    ln_kernel<2, 4><<<BQ, 256>>>(ln2_g, ln2_b);
    // 6) b_ffn = bf16(gelu(b_h @ w_f1^T + b_ffn1))
    tgemm<2, 4, 4, 0, 0, 0, 5><<<dim3(8, BQ / 128), 256>>>(
        b_ffn1, nullptr, nullptr, BQ, FDIM, CDIM);
    // 7) out = g_x + b_ffn @ w_f2^T + b_ffn2
    tgemm<1, 5, 5, 0, 2, 0, 0><<<dim3(2, BQ / 128), 256>>>(
        b_ffn2, nullptr, out, BQ, CDIM, FDIM);
}